// round 13
// baseline (speedup 1.0000x reference)
#include <cuda_runtime.h>
#include <cuda_fp16.h>
#include <cstdint>

// Problem constants (fixed shapes per reference)
#define DIMC 128
#define KC   65536
#define BC   1024
#define LC   512
#define PC   8388608

// Pool layout: [keyN 128 | trans 2048 | EMA 2048 | gather 1024 | EMA 6144]
#define NB_KEYN   128
#define NB_TRANS  2048
#define NB_EMA1   2048
#define NB_GATHER 1024
#define NB_EMA2   6144
#define BID_TRANS  NB_KEYN                       // 128
#define BID_EMA1   (BID_TRANS + NB_TRANS)        // 2176
#define BID_GATHER (BID_EMA1 + NB_EMA1)          // 4224
#define BID_EMA2   (BID_GATHER + NB_GATHER)      // 5248
#define NB_TOTAL   (BID_EMA2 + NB_EMA2)          // 11392
#define CTR_KEYS   NB_KEYN                       // 128
#define CTR_TRANS  (NB_KEYN + NB_TRANS)          // 2176

// Scratch (device globals — no allocation allowed)
__device__ __half   g_qTh[(size_t)KC * DIMC];   // 16 MB transposed queue, fp16
__device__ float    g_keysN[BC * DIMC];         // normalized keys
__device__ unsigned g_ctr = 0;                  // producer-completion counter

__device__ __forceinline__ void wait_ctr(unsigned target) {
    if (threadIdx.x == 0) {
        while (atomicAdd(&g_ctr, 0u) < target)
            __nanosleep(64);
        __threadfence();
    }
    __syncthreads();
}

__device__ __forceinline__ void ema_do(const float* __restrict__ pq,
                                       const float* __restrict__ pk,
                                       float* __restrict__ new_pk, int i) {
    float4 a  = __ldcs(reinterpret_cast<const float4*>(pq) + i);
    float4 b4 = __ldcs(reinterpret_cast<const float4*>(pk) + i);
    float4 r = make_float4(b4.x * 0.7f + a.x * 0.3f,
                           b4.y * 0.7f + a.y * 0.3f,
                           b4.z * 0.7f + a.z * 0.3f,
                           b4.w * 0.7f + a.w * 0.3f);
    __stcs(reinterpret_cast<float4*>(new_pk) + i, r);
}

// ---------------------------------------------------------------------------
// Single pool kernel. 11392 blocks x 256 threads.
// ---------------------------------------------------------------------------
__global__ __launch_bounds__(256) void moco_pool_kernel(
        const float* __restrict__ q,
        const int* __restrict__ sidx,
        const float* __restrict__ queue,
        const float* __restrict__ keys,
        const float* __restrict__ pq,
        const float* __restrict__ pk,
        const int* __restrict__ ptrp,
        float* __restrict__ logits,
        float* __restrict__ labels,
        float* __restrict__ new_queue,
        float* __restrict__ new_pk) {
    int bid = blockIdx.x;

    if (bid < NB_KEYN) {
        // ---- key-normalize producer: one warp per key row (8 rows/block) ----
        int gw   = bid * 8 + (threadIdx.x >> 5);   // 0..1023
        int lane = threadIdx.x & 31;
        float4 v = reinterpret_cast<const float4*>(keys + (size_t)gw * DIMC)[lane];
        float s = v.x * v.x + v.y * v.y + v.z * v.z + v.w * v.w;
        #pragma unroll
        for (int o = 16; o > 0; o >>= 1) s += __shfl_xor_sync(0xFFFFFFFFu, s, o);
        float inv = 1.0f / sqrtf(s);
        reinterpret_cast<float4*>(g_keysN + (size_t)gw * DIMC)[lane] =
            make_float4(v.x * inv, v.y * inv, v.z * inv, v.w * inv);
        __threadfence();
        __syncthreads();
        if (threadIdx.x == 0) atomicAdd(&g_ctr, 1u);

    } else if (bid < BID_EMA1) {
        // ---- transpose + new_queue producer: 32 k-cols x 128 dims ----
        __shared__ float tile[32][129];
        int tb   = bid - BID_TRANS;        // 0..2047
        int k0   = tb << 5;
        int lane = threadIdx.x & 31;
        int wy   = threadIdx.x >> 5;       // warp 0..7
        int ptr  = *ptrp;

        #pragma unroll
        for (int i = 0; i < 16; ++i) {
            int d = wy * 16 + i;
            tile[lane][d] = __ldg(&queue[(size_t)d * KC + (k0 + lane)]);
        }
        __syncthreads();

        #pragma unroll
        for (int j = 0; j < 4; ++j) {
            int k = wy * 4 + j;
            float v0 = tile[k][4 * lane + 0];
            float v1 = tile[k][4 * lane + 1];
            float v2 = tile[k][4 * lane + 2];
            float v3 = tile[k][4 * lane + 3];
            __half2 h0 = __floats2half2_rn(v0, v1);
            __half2 h1 = __floats2half2_rn(v2, v3);
            uint2 pkt = make_uint2(*reinterpret_cast<unsigned*>(&h0),
                                   *reinterpret_cast<unsigned*>(&h1));
            *reinterpret_cast<uint2*>(&g_qTh[(size_t)(k0 + k) * DIMC + 4 * lane]) = pkt;
        }

        __threadfence();
        __syncthreads();
        if (threadIdx.x == 0) atomicAdd(&g_ctr, 1u);

        int lo = ptr - k0;          if (lo < 0)  lo = 0;
        int hi = ptr + BC - k0;     if (hi > 32) hi = 32;
        if (lo < hi) {
            wait_ctr(CTR_KEYS);
            for (int k = lo + wy; k < hi; k += 8) {
                int r = k0 + k - ptr;
                float4 v = reinterpret_cast<const float4*>(g_keysN + (size_t)r * DIMC)[lane];
                tile[k][4 * lane + 0] = v.x;
                tile[k][4 * lane + 1] = v.y;
                tile[k][4 * lane + 2] = v.z;
                tile[k][4 * lane + 3] = v.w;
            }
            __syncthreads();
        }

        #pragma unroll
        for (int i = 0; i < 16; ++i) {
            int d = wy * 16 + i;
            __stcs(&new_queue[(size_t)d * KC + (k0 + lane)], tile[lane][d]);
        }

    } else if (bid < BID_GATHER) {
        // ---- EMA stream, front slice ----
        ema_do(pq, pk, new_pk, (bid - BID_EMA1) * 256 + (int)threadIdx.x);

    } else if (bid < BID_EMA2) {
        // ---- logits gather: 8 lanes/sample, 4 samples/warp-iter ----
        int b = bid - BID_GATHER;
        __shared__ float4 qs4[32];
        int tid = threadIdx.x;
        if (tid < 32) {
            float4 v = reinterpret_cast<const float4*>(q + (size_t)b * DIMC)[tid];
            float s = v.x * v.x + v.y * v.y + v.z * v.z + v.w * v.w;
            #pragma unroll
            for (int o = 16; o > 0; o >>= 1) s += __shfl_xor_sync(0xFFFFFFFFu, s, o);
            float inv = 1.0f / sqrtf(s);
            qs4[tid] = make_float4(v.x * inv, v.y * inv, v.z * inv, v.w * inv);
        }
        if (tid == 0) labels[b] = 0.0f;

        wait_ctr(CTR_TRANS);

        int lane    = tid & 31;
        int warp    = tid >> 5;      // 0..7
        int quarter = lane >> 3;     // 0..3 : which of 4 samples this lane serves
        int sub8    = lane & 7;      // position within the 8-lane group

        // this lane's 16 q-values (dims sub8*16 .. sub8*16+15)
        float4 q0 = qs4[sub8 * 4 + 0];
        float4 q1 = qs4[sub8 * 4 + 1];
        float4 q2 = qs4[sub8 * 4 + 2];
        float4 q3 = qs4[sub8 * 4 + 3];

        const int* row = sidx + (size_t)b * LC;
        float* lrow = logits + (size_t)b * LC;

        // warp handles samples l = warp*4 + quarter + i*32, i = 0..15
        #pragma unroll 4
        for (int l0 = warp * 4; l0 < LC; l0 += 32) {
            int idx = row[l0 + quarter];
            const int4* src = reinterpret_cast<const int4*>(g_qTh + (size_t)idx * DIMC);
            int4 pa = src[sub8 * 2 + 0];
            int4 pb = src[sub8 * 2 + 1];

            float2 a0 = __half22float2(*reinterpret_cast<__half2*>(&pa.x));
            float2 a1 = __half22float2(*reinterpret_cast<__half2*>(&pa.y));
            float2 a2 = __half22float2(*reinterpret_cast<__half2*>(&pa.z));
            float2 a3 = __half22float2(*reinterpret_cast<__half2*>(&pa.w));
            float2 b0 = __half22float2(*reinterpret_cast<__half2*>(&pb.x));
            float2 b1 = __half22float2(*reinterpret_cast<__half2*>(&pb.y));
            float2 b2 = __half22float2(*reinterpret_cast<__half2*>(&pb.z));
            float2 b3 = __half22float2(*reinterpret_cast<__half2*>(&pb.w));

            float s = a0.x * q0.x + a0.y * q0.y + a1.x * q0.z + a1.y * q0.w
                    + a2.x * q1.x + a2.y * q1.y + a3.x * q1.z + a3.y * q1.w
                    + b0.x * q2.x + b0.y * q2.y + b1.x * q2.z + b1.y * q2.w
                    + b2.x * q3.x + b2.y * q3.y + b3.x * q3.z + b3.y * q3.w;

            // 3-step reduce within the 8-lane group
            s += __shfl_xor_sync(0xFFFFFFFFu, s, 4);
            s += __shfl_xor_sync(0xFFFFFFFFu, s, 2);
            s += __shfl_xor_sync(0xFFFFFFFFu, s, 1);

            if (sub8 == 0)
                lrow[l0 + quarter] = s * (1.0f / 0.09f);
        }

    } else {
        // ---- EMA stream, back slice ----
        int ema_id = NB_EMA1 + (bid - BID_EMA2);
        ema_do(pq, pk, new_pk, ema_id * 256 + (int)threadIdx.x);
    }
}

// ---------------------------------------------------------------------------
extern "C" void kernel_launch(void* const* d_in, const int* in_sizes, int n_in,
                              void* d_out, int out_size) {
    const float* q        = (const float*)d_in[0];
    const float* queue    = (const float*)d_in[1];
    const float* keys     = (const float*)d_in[2];
    const float* param_q  = (const float*)d_in[3];
    const float* param_k  = (const float*)d_in[4];
    const int*   sidx     = (const int*)  d_in[5];
    const int*   ptr      = (const int*)  d_in[6];

    float* out       = (float*)d_out;
    float* logits    = out;                            // B*L = 524288
    float* labels    = logits + (size_t)BC * LC;       // 1024
    float* new_queue = labels + BC;                    // DIM*K = 8388608
    float* new_pk    = new_queue + (size_t)DIMC * KC;  // P = 8388608

    // One launch: [keyN | trans(+copy) | EMA | gather | EMA]
    moco_pool_kernel<<<NB_TOTAL, 256>>>(
        q, sidx, queue, keys, param_q, param_k, ptr,
        logits, labels, new_queue, new_pk);
}

// round 14
// speedup vs baseline: 1.1105x; 1.1105x over previous
#include <cuda_runtime.h>
#include <cuda_fp16.h>
#include <cstdint>

// Problem constants (fixed shapes per reference)
#define DIMC 128
#define KC   65536
#define BC   1024
#define LC   512
#define PC   8388608

// Pool layout: [keyN 128 | trans 2048 | EMA 2048 | gather 1024 | EMA 6144]
#define NB_KEYN   128
#define NB_TRANS  2048
#define NB_EMA1   2048
#define NB_GATHER 1024
#define NB_EMA2   6144
#define BID_TRANS  NB_KEYN                       // 128
#define BID_EMA1   (BID_TRANS + NB_TRANS)        // 2176
#define BID_GATHER (BID_EMA1 + NB_EMA1)          // 4224
#define BID_EMA2   (BID_GATHER + NB_GATHER)      // 5248
#define NB_TOTAL   (BID_EMA2 + NB_EMA2)          // 11392
#define CTR_KEYS   NB_KEYN                       // 128
#define CTR_TRANS  (NB_KEYN + NB_TRANS)          // 2176

// Scratch (device globals — no allocation allowed)
__device__ __half   g_qTh[(size_t)KC * DIMC];   // 16 MB transposed queue, fp16
__device__ float    g_keysN[BC * DIMC];         // normalized keys
__device__ unsigned g_ctr = 0;                  // producer-completion counter

__device__ __forceinline__ void wait_ctr(unsigned target) {
    if (threadIdx.x == 0) {
        while (atomicAdd(&g_ctr, 0u) < target)
            __nanosleep(64);
        __threadfence();
    }
    __syncthreads();
}

__device__ __forceinline__ void ema_do(const float* __restrict__ pq,
                                       const float* __restrict__ pk,
                                       float* __restrict__ new_pk, int i) {
    float4 a  = __ldcs(reinterpret_cast<const float4*>(pq) + i);
    float4 b4 = __ldcs(reinterpret_cast<const float4*>(pk) + i);
    float4 r = make_float4(b4.x * 0.7f + a.x * 0.3f,
                           b4.y * 0.7f + a.y * 0.3f,
                           b4.z * 0.7f + a.z * 0.3f,
                           b4.w * 0.7f + a.w * 0.3f);
    __stcs(reinterpret_cast<float4*>(new_pk) + i, r);
}

// ---------------------------------------------------------------------------
// Single pool kernel. 11392 blocks x 256 threads.
// ---------------------------------------------------------------------------
__global__ __launch_bounds__(256) void moco_pool_kernel(
        const float* __restrict__ q,
        const int* __restrict__ sidx,
        const float* __restrict__ queue,
        const float* __restrict__ keys,
        const float* __restrict__ pq,
        const float* __restrict__ pk,
        const int* __restrict__ ptrp,
        float* __restrict__ logits,
        float* __restrict__ labels,
        float* __restrict__ new_queue,
        float* __restrict__ new_pk) {
    int bid = blockIdx.x;

    if (bid < NB_KEYN) {
        // ---- key-normalize producer: one warp per key row (8 rows/block) ----
        int gw   = bid * 8 + (threadIdx.x >> 5);   // 0..1023
        int lane = threadIdx.x & 31;
        float4 v = reinterpret_cast<const float4*>(keys + (size_t)gw * DIMC)[lane];
        float s = v.x * v.x + v.y * v.y + v.z * v.z + v.w * v.w;
        #pragma unroll
        for (int o = 16; o > 0; o >>= 1) s += __shfl_xor_sync(0xFFFFFFFFu, s, o);
        float inv = 1.0f / sqrtf(s);
        reinterpret_cast<float4*>(g_keysN + (size_t)gw * DIMC)[lane] =
            make_float4(v.x * inv, v.y * inv, v.z * inv, v.w * inv);
        __threadfence();
        __syncthreads();
        if (threadIdx.x == 0) atomicAdd(&g_ctr, 1u);

    } else if (bid < BID_EMA1) {
        // ---- transpose + new_queue producer: 32 k-cols x 128 dims ----
        __shared__ float tile[32][129];
        int tb   = bid - BID_TRANS;        // 0..2047
        int k0   = tb << 5;
        int lane = threadIdx.x & 31;
        int wy   = threadIdx.x >> 5;       // warp 0..7
        int ptr  = *ptrp;

        // Phase 1: load 128 rows x 32 cols (tile[k_local][d])
        #pragma unroll
        for (int i = 0; i < 16; ++i) {
            int d = wy * 16 + i;
            tile[lane][d] = __ldg(&queue[(size_t)d * KC + (k0 + lane)]);
        }
        __syncthreads();

        // Phase 2: fp16 transposed store of ORIGINAL values
        #pragma unroll
        for (int j = 0; j < 4; ++j) {
            int k = wy * 4 + j;
            float v0 = tile[k][4 * lane + 0];
            float v1 = tile[k][4 * lane + 1];
            float v2 = tile[k][4 * lane + 2];
            float v3 = tile[k][4 * lane + 3];
            __half2 h0 = __floats2half2_rn(v0, v1);
            __half2 h1 = __floats2half2_rn(v2, v3);
            uint2 pkt = make_uint2(*reinterpret_cast<unsigned*>(&h0),
                                   *reinterpret_cast<unsigned*>(&h1));
            *reinterpret_cast<uint2*>(&g_qTh[(size_t)(k0 + k) * DIMC + 4 * lane]) = pkt;
        }

        // signal qTh done for this block BEFORE the (rare) keysN wait
        __threadfence();
        __syncthreads();
        if (threadIdx.x == 0) atomicAdd(&g_ctr, 1u);

        // Phase 3: replaced columns <- normalized keys (only ~32 blocks)
        int lo = ptr - k0;          if (lo < 0)  lo = 0;
        int hi = ptr + BC - k0;     if (hi > 32) hi = 32;
        if (lo < hi) {
            wait_ctr(CTR_KEYS);
            for (int k = lo + wy; k < hi; k += 8) {
                int r = k0 + k - ptr;
                float4 v = reinterpret_cast<const float4*>(g_keysN + (size_t)r * DIMC)[lane];
                tile[k][4 * lane + 0] = v.x;
                tile[k][4 * lane + 1] = v.y;
                tile[k][4 * lane + 2] = v.z;
                tile[k][4 * lane + 3] = v.w;
            }
            __syncthreads();
        }

        // Phase 4: write new_queue rows, vectorized float4 along k.
        // j = g*256+tid covers 1024 float4s: d = j/8, k-offset = (j%8)*4.
        // smem bank = (k*129+d)%32 = (k+d)%32 -> conflict-free per warp.
        #pragma unroll
        for (int g = 0; g < 4; ++g) {
            int j  = g * 256 + (int)threadIdx.x;
            int d  = j >> 3;
            int kq = (j & 7) << 2;
            float4 v = make_float4(tile[kq + 0][d], tile[kq + 1][d],
                                   tile[kq + 2][d], tile[kq + 3][d]);
            __stcs(reinterpret_cast<float4*>(&new_queue[(size_t)d * KC + k0 + kq]), v);
        }

    } else if (bid < BID_GATHER) {
        // ---- EMA stream, front slice ----
        ema_do(pq, pk, new_pk, (bid - BID_EMA1) * 256 + (int)threadIdx.x);

    } else if (bid < BID_EMA2) {
        // ---- logits gather consumer (R12/R3 proven loop, regs=32) ----
        int b = bid - BID_GATHER;
        __shared__ float4 qs4[32];
        int tid = threadIdx.x;
        if (tid < 32) {
            float4 v = reinterpret_cast<const float4*>(q + (size_t)b * DIMC)[tid];
            float s = v.x * v.x + v.y * v.y + v.z * v.z + v.w * v.w;
            #pragma unroll
            for (int o = 16; o > 0; o >>= 1) s += __shfl_xor_sync(0xFFFFFFFFu, s, o);
            float inv = 1.0f / sqrtf(s);
            qs4[tid] = make_float4(v.x * inv, v.y * inv, v.z * inv, v.w * inv);
        }
        if (tid == 0) labels[b] = 0.0f;

        wait_ctr(CTR_TRANS);

        int lane    = tid & 31;
        int warp    = tid >> 5;
        int half_id = lane >> 4;
        int subl    = lane & 15;

        float4 qa = qs4[subl * 2];
        float4 qb = qs4[subl * 2 + 1];

        const int* row = sidx + (size_t)b * LC;
        float* lrow = logits + (size_t)b * LC;

        #pragma unroll 4
        for (int l = warp * 2; l < LC; l += 16) {
            int idx = row[l + half_id];
            int4 pkt = reinterpret_cast<const int4*>(g_qTh + (size_t)idx * DIMC)[subl];
            float2 f0 = __half22float2(*reinterpret_cast<__half2*>(&pkt.x));
            float2 f1 = __half22float2(*reinterpret_cast<__half2*>(&pkt.y));
            float2 f2 = __half22float2(*reinterpret_cast<__half2*>(&pkt.z));
            float2 f3 = __half22float2(*reinterpret_cast<__half2*>(&pkt.w));
            float s = f0.x * qa.x + f0.y * qa.y + f1.x * qa.z + f1.y * qa.w
                    + f2.x * qb.x + f2.y * qb.y + f3.x * qb.z + f3.y * qb.w;
            #pragma unroll
            for (int o = 8; o > 0; o >>= 1)
                s += __shfl_xor_sync(0xFFFFFFFFu, s, o);
            if (subl == 0)
                lrow[l + half_id] = s * (1.0f / 0.09f);
        }

    } else {
        // ---- EMA stream, back slice ----
        int ema_id = NB_EMA1 + (bid - BID_EMA2);
        ema_do(pq, pk, new_pk, ema_id * 256 + (int)threadIdx.x);
    }
}

// ---------------------------------------------------------------------------
extern "C" void kernel_launch(void* const* d_in, const int* in_sizes, int n_in,
                              void* d_out, int out_size) {
    const float* q        = (const float*)d_in[0];
    const float* queue    = (const float*)d_in[1];
    const float* keys     = (const float*)d_in[2];
    const float* param_q  = (const float*)d_in[3];
    const float* param_k  = (const float*)d_in[4];
    const int*   sidx     = (const int*)  d_in[5];
    const int*   ptr      = (const int*)  d_in[6];

    float* out       = (float*)d_out;
    float* logits    = out;                            // B*L = 524288
    float* labels    = logits + (size_t)BC * LC;       // 1024
    float* new_queue = labels + BC;                    // DIM*K = 8388608
    float* new_pk    = new_queue + (size_t)DIMC * KC;  // P = 8388608

    // One launch: [keyN | trans(+copy) | EMA | gather | EMA]
    moco_pool_kernel<<<NB_TOTAL, 256>>>(
        q, sidx, queue, keys, param_q, param_k, ptr,
        logits, labels, new_queue, new_pk);
}